// round 1
// baseline (speedup 1.0000x reference)
#include <cuda_runtime.h>
#include <math.h>

#define NB 16
#define NTT 27
#define NC 128
#define CHN 12
#define K1 324
#define N1 256
#define N2 128
#define ROWS 16384   // 128*128
#define TM 64

// Scratch (device globals — no runtime allocation)
__device__ float g_H[(size_t)NB * N2 * ROWS];   // [b][z][row]  ~128 MB
__device__ float g_P[NB * 8 * N2];              // pooled + vector_log, [b][q*128+z]
__device__ float g_H2[NB * N1];                 // relu(P@W3+b3)

// ---- packed fp32x2 helpers (FFMA2 path, PTX-only per sm_103a) ----
__device__ __forceinline__ unsigned long long pack2(float x, float y) {
    unsigned long long r;
    asm("mov.b64 %0, {%1, %2};" : "=l"(r) : "f"(x), "f"(y));
    return r;
}
__device__ __forceinline__ void fma2(unsigned long long& d,
                                     unsigned long long a, unsigned long long b) {
    asm("fma.rn.f32x2 %0, %1, %2, %0;" : "+l"(d) : "l"(a), "l"(b));
}
__device__ __forceinline__ float2 unpack2(unsigned long long v) {
    float lo, hi;
    asm("mov.b64 {%0, %1}, %2;" : "=f"(lo), "=f"(hi) : "l"(v));
    return make_float2(lo, hi);
}

// ============================================================
// Kernel 1: fused  relu(X@W1+b1)@W2+b2  ->  g_H[b][z][row]
// CTA: 64 rows x full N. 256 threads, thread tile 8x8 (stage1) / 8x4 (stage2),
// all accumulation on fma.rn.f32x2.
// ============================================================
__global__ void __launch_bounds__(256, 2) gemm12_kernel(
    const float* __restrict__ fgc, const float* __restrict__ fgt,
    const float* __restrict__ bgc, const float* __restrict__ bgt,
    const float* __restrict__ W1, const float* __restrict__ b1,
    const float* __restrict__ W2, const float* __restrict__ b2)
{
    extern __shared__ float sm[];
    float* As  = sm;                  // 64*12
    float* Ws1 = As + TM * CHN;       // 12*256
    float* C1s = Ws1 + CHN * N1;      // 64*256 (later reused as 64x129 transpose buf)
    float* Ws2 = C1s + TM * N1;       // 64*128

    const int tid  = threadIdx.x;
    const int b    = blockIdx.y;
    const int row0 = blockIdx.x * TM;
    const int warp = tid >> 5, lane = tid & 31;
    const int r0 = warp * 8;          // 8 warps -> rows 0..63
    const int c0 = lane * 8;          // cols 0..255

    unsigned long long acc[8][4];
    #pragma unroll
    for (int i = 0; i < 8; ++i)
        #pragma unroll
        for (int j = 0; j < 4; ++j) acc[i][j] = 0ULL;

    // ---- stage 1: C1 = relu(X @ W1 + b1), K streamed per t-slice (12 k each)
    const size_t bbase = (size_t)b * NTT * ROWS * 3;
    for (int t = 0; t < NTT; ++t) {
        const size_t tbase = bbase + (size_t)t * ROWS * 3 + (size_t)row0 * 3;
        for (int idx = tid; idx < TM * CHN; idx += 256) {
            int r = idx / CHN, kk = idx - r * CHN;
            int src = kk / 3, c3 = kk - src * 3;
            const float* sp = (src == 0) ? fgc : ((src == 1) ? fgt : ((src == 2) ? bgc : bgt));
            As[r * CHN + kk] = sp[tbase + (size_t)r * 3 + c3];
        }
        const float* w1p = W1 + (size_t)t * CHN * N1;   // 12 contiguous rows
        for (int idx = tid; idx < CHN * N1; idx += 256) Ws1[idx] = w1p[idx];
        __syncthreads();

        #pragma unroll
        for (int kk = 0; kk < CHN; ++kk) {
            unsigned long long a2[8], w2v[4];
            #pragma unroll
            for (int i = 0; i < 8; ++i) {
                float av = As[(r0 + i) * CHN + kk];     // per-warp broadcast
                a2[i] = pack2(av, av);
            }
            const float4* wr = (const float4*)(Ws1 + kk * N1 + c0);
            float4 wa = wr[0], wb = wr[1];
            w2v[0] = pack2(wa.x, wa.y); w2v[1] = pack2(wa.z, wa.w);
            w2v[2] = pack2(wb.x, wb.y); w2v[3] = pack2(wb.z, wb.w);
            #pragma unroll
            for (int i = 0; i < 8; ++i)
                #pragma unroll
                for (int j = 0; j < 4; ++j) fma2(acc[i][j], a2[i], w2v[j]);
        }
        __syncthreads();
    }

    // relu + b1 -> C1s[64][256]
    #pragma unroll
    for (int i = 0; i < 8; ++i)
        #pragma unroll
        for (int j = 0; j < 4; ++j) {
            float2 v = unpack2(acc[i][j]);
            int col = c0 + 2 * j;
            C1s[(r0 + i) * N1 + col]     = fmaxf(v.x + b1[col], 0.f);
            C1s[(r0 + i) * N1 + col + 1] = fmaxf(v.y + b1[col + 1], 0.f);
        }
    __syncthreads();

    // ---- stage 2: C2 = C1 @ W2 + b2
    unsigned long long acc2[8][2];
    #pragma unroll
    for (int i = 0; i < 8; ++i) { acc2[i][0] = 0ULL; acc2[i][1] = 0ULL; }
    const int c2 = lane * 4;          // cols 0..127

    for (int k0 = 0; k0 < N1; k0 += 64) {
        const float* w2p = W2 + (size_t)k0 * N2;        // 64 contiguous rows
        for (int idx = tid; idx < 64 * N2; idx += 256) Ws2[idx] = w2p[idx];
        __syncthreads();
        #pragma unroll 8
        for (int kk = 0; kk < 64; ++kk) {
            unsigned long long a2[8];
            #pragma unroll
            for (int i = 0; i < 8; ++i) {
                float av = C1s[(r0 + i) * N1 + k0 + kk]; // broadcast
                a2[i] = pack2(av, av);
            }
            float4 w = *(const float4*)(Ws2 + kk * N2 + c2);
            unsigned long long wv0 = pack2(w.x, w.y), wv1 = pack2(w.z, w.w);
            #pragma unroll
            for (int i = 0; i < 8; ++i) {
                fma2(acc2[i][0], a2[i], wv0);
                fma2(acc2[i][1], a2[i], wv1);
            }
        }
        __syncthreads();
    }

    // ---- epilogue: +b2, transpose via padded SMEM, store H[b][z][row]
    float* Tb = C1s;   // reuse, stride 129 (conflict-free transposed read)
    #pragma unroll
    for (int i = 0; i < 8; ++i)
        #pragma unroll
        for (int j = 0; j < 2; ++j) {
            float2 v = unpack2(acc2[i][j]);
            int col = c2 + 2 * j;
            Tb[(r0 + i) * 129 + col]     = v.x + b2[col];
            Tb[(r0 + i) * 129 + col + 1] = v.y + b2[col + 1];
        }
    __syncthreads();
    float* hb = g_H + (size_t)b * N2 * ROWS + row0;
    for (int e = tid; e < TM * N2; e += 256) {
        int z = e >> 6, rr = e & 63;
        hb[(size_t)z * ROWS + rr] = Tb[rr * 129 + z];    // 256B coalesced segments
    }
}

// ============================================================
// Kernel 2: invariant pooling + vector_log.
// CTA per (b,z): 128x128 slice in SMEM (stride 129), thread a owns row a.
// Denominators are constants (pad channel is all-ones).
// ============================================================
__global__ void pool_kernel()
{
    extern __shared__ float S[];       // 128*129 floats
    const int tid = threadIdx.x;       // 128 threads
    const int bz = blockIdx.x;
    const float* src = g_H + (size_t)bz * ROWS;

    for (int e = tid; e < ROWS; e += 128)
        S[(e >> 7) * 129 + (e & 127)] = src[e];
    __syncthreads();

    const int a = tid;
    const float* rowp = S + a * 129;
    float d = rowp[a];
    float r = 0.f, c = 0.f, p4 = 0.f, p5 = 0.f;
    #pragma unroll 4
    for (int bb = 0; bb < 128; ++bb) {
        float xab = rowp[bb];            // stride-129 across threads: conflict-free
        float xba = S[bb * 129 + a];     // stride-1 across threads: conflict-free
        r += xab; c += xba;
        p4 = fmaf(xab, xab, p4);
        p5 = fmaf(xab, xba, p5);
    }
    float vals[8] = { d, r, d * d, d * r, p4, p5, r * r, r * c };
    __syncthreads();                     // done reading S, reuse front for reduction

    float* red = S;                      // [4 warps][8]
    #pragma unroll
    for (int q = 0; q < 8; ++q) {
        float v = vals[q];
        #pragma unroll
        for (int off = 16; off > 0; off >>= 1)
            v += __shfl_down_sync(0xffffffff, v, off);
        if ((tid & 31) == 0) red[(tid >> 5) * 8 + q] = v;
    }
    __syncthreads();
    if (tid < 8) {
        float h = red[tid] + red[8 + tid] + red[16 + tid] + red[24 + tid];
        const float denom[8] = {128.f, 16384.f, 128.f, 16384.f,
                                16384.f, 16384.f, 2097152.f, 2097152.f};
        float p = h / denom[tid];
        float vl = copysignf(log1pf(fabsf(p)) * 0.1f, p);
        int b = bz >> 7, z = bz & 127;
        g_P[b * 1024 + tid * 128 + z] = vl;
    }
}

// ============================================================
// Kernel 3a: H2 = relu(P @ W3 + b3)   [16 x 256]
// ============================================================
__global__ void mlp2a_kernel(const float* __restrict__ W3, const float* __restrict__ b3)
{
    const int tid = threadIdx.x;             // 256
    const int n = blockIdx.x * 16 + (tid & 15);
    const int r = tid >> 4;
    const float* p = g_P + r * 1024;
    float acc = b3[n];
    #pragma unroll 8
    for (int k = 0; k < 1024; ++k)
        acc = fmaf(p[k], W3[k * 256 + n], acc);
    g_H2[r * 256 + n] = fmaxf(acc, 0.f);
}

// ============================================================
// Kernel 3b: out = tanh(H2 @ W4 + b4) * 8   [16 x 2]
// ============================================================
__global__ void mlp2b_kernel(const float* __restrict__ W4, const float* __restrict__ b4,
                             float* __restrict__ out)
{
    const int t = threadIdx.x;  // 32
    const int r = t >> 1, c = t & 1;
    float s = b4[c];
    #pragma unroll 8
    for (int k = 0; k < 256; ++k)
        s = fmaf(g_H2[r * 256 + k], W4[k * 2 + c], s);
    out[t] = tanhf(s) * 8.0f;
}

// ============================================================
extern "C" void kernel_launch(void* const* d_in, const int* in_sizes, int n_in,
                              void* d_out, int out_size)
{
    const float* fgc = (const float*)d_in[0];
    const float* fgt = (const float*)d_in[1];
    const float* bgc = (const float*)d_in[2];
    const float* bgt = (const float*)d_in[3];
    const float* W1  = (const float*)d_in[4];
    const float* b1  = (const float*)d_in[5];
    const float* W2  = (const float*)d_in[6];
    const float* b2  = (const float*)d_in[7];
    const float* W3  = (const float*)d_in[8];
    const float* b3  = (const float*)d_in[9];
    const float* W4  = (const float*)d_in[10];
    const float* b4  = (const float*)d_in[11];
    float* out = (float*)d_out;

    const int SMEM1 = (TM * CHN + CHN * N1 + TM * N1 + 64 * N2) * 4;  // 113664 B
    const int SMEM2 = 128 * 129 * 4;                                  // 66048 B
    cudaFuncSetAttribute(gemm12_kernel, cudaFuncAttributeMaxDynamicSharedMemorySize, SMEM1);
    cudaFuncSetAttribute(pool_kernel,   cudaFuncAttributeMaxDynamicSharedMemorySize, SMEM2);

    gemm12_kernel<<<dim3(ROWS / TM, NB), 256, SMEM1>>>(fgc, fgt, bgc, bgt, W1, b1, W2, b2);
    pool_kernel<<<NB * N2, 128, SMEM2>>>();
    mlp2a_kernel<<<16, 256>>>(W3, b3);
    mlp2b_kernel<<<1, 32>>>(W4, b4, out);
}

// round 2
// speedup vs baseline: 1.2712x; 1.2712x over previous
#include <cuda_runtime.h>
#include <math.h>

#define NB 16
#define NTT 27
#define NC 128
#define CHN 12
#define K1 324
#define N1 256
#define N2 128
#define ROWS 16384   // 128*128
#define TM 64

// Scratch (device globals — no runtime allocation)
__device__ float g_H[(size_t)NB * N2 * ROWS];   // [b][z][row]  ~128 MB
__device__ float g_P[NB * 8 * N2];              // pooled + vector_log, [b][q*128+z]
__device__ float g_H2[NB * N1];                 // relu(P@W3+b3)

// ---- packed fp32x2 helpers (FFMA2 path, PTX-only per sm_103a) ----
__device__ __forceinline__ unsigned long long pack2(float x, float y) {
    unsigned long long r;
    asm("mov.b64 %0, {%1, %2};" : "=l"(r) : "f"(x), "f"(y));
    return r;
}
__device__ __forceinline__ void fma2(unsigned long long& d,
                                     unsigned long long a, unsigned long long b) {
    asm("fma.rn.f32x2 %0, %1, %2, %0;" : "+l"(d) : "l"(a), "l"(b));
}
__device__ __forceinline__ float2 unpack2(unsigned long long v) {
    float lo, hi;
    asm("mov.b64 {%0, %1}, %2;" : "=f"(lo), "=f"(hi) : "l"(v));
    return make_float2(lo, hi);
}

// ============================================================
// Kernel 1: fused  relu(X@W1+b1)@W2+b2  ->  g_H[b][z][row]
// CTA: 64 rows x full N. 256 threads, thread tile 8x8 (stage1) / 8x4 (stage2),
// all accumulation on fma.rn.f32x2.
// ============================================================
__global__ void __launch_bounds__(256, 2) gemm12_kernel(
    const float* __restrict__ fgc, const float* __restrict__ fgt,
    const float* __restrict__ bgc, const float* __restrict__ bgt,
    const float* __restrict__ W1, const float* __restrict__ b1,
    const float* __restrict__ W2, const float* __restrict__ b2)
{
    extern __shared__ float sm[];
    float* As  = sm;                  // 64*12
    float* Ws1 = As + TM * CHN;       // 12*256
    float* C1s = Ws1 + CHN * N1;      // 64*256 (later reused as 64x129 transpose buf)
    float* Ws2 = C1s + TM * N1;       // 64*128

    const int tid  = threadIdx.x;
    const int b    = blockIdx.y;
    const int row0 = blockIdx.x * TM;
    const int warp = tid >> 5, lane = tid & 31;
    const int r0 = warp * 8;          // 8 warps -> rows 0..63
    const int c0 = lane * 8;          // cols 0..255

    unsigned long long acc[8][4];
    #pragma unroll
    for (int i = 0; i < 8; ++i)
        #pragma unroll
        for (int j = 0; j < 4; ++j) acc[i][j] = 0ULL;

    // ---- stage 1: C1 = relu(X @ W1 + b1), K streamed per t-slice (12 k each)
    const size_t bbase = (size_t)b * NTT * ROWS * 3;
    for (int t = 0; t < NTT; ++t) {
        const size_t tbase = bbase + (size_t)t * ROWS * 3 + (size_t)row0 * 3;
        for (int idx = tid; idx < TM * CHN; idx += 256) {
            int r = idx / CHN, kk = idx - r * CHN;
            int src = kk / 3, c3 = kk - src * 3;
            const float* sp = (src == 0) ? fgc : ((src == 1) ? fgt : ((src == 2) ? bgc : bgt));
            As[r * CHN + kk] = sp[tbase + (size_t)r * 3 + c3];
        }
        const float* w1p = W1 + (size_t)t * CHN * N1;   // 12 contiguous rows
        for (int idx = tid; idx < CHN * N1; idx += 256) Ws1[idx] = w1p[idx];
        __syncthreads();

        #pragma unroll
        for (int kk = 0; kk < CHN; ++kk) {
            unsigned long long a2[8], w2v[4];
            #pragma unroll
            for (int i = 0; i < 8; ++i) {
                float av = As[(r0 + i) * CHN + kk];     // per-warp broadcast
                a2[i] = pack2(av, av);
            }
            const float4* wr = (const float4*)(Ws1 + kk * N1 + c0);
            float4 wa = wr[0], wb = wr[1];
            w2v[0] = pack2(wa.x, wa.y); w2v[1] = pack2(wa.z, wa.w);
            w2v[2] = pack2(wb.x, wb.y); w2v[3] = pack2(wb.z, wb.w);
            #pragma unroll
            for (int i = 0; i < 8; ++i)
                #pragma unroll
                for (int j = 0; j < 4; ++j) fma2(acc[i][j], a2[i], w2v[j]);
        }
        __syncthreads();
    }

    // relu + b1 -> C1s[64][256]
    #pragma unroll
    for (int i = 0; i < 8; ++i)
        #pragma unroll
        for (int j = 0; j < 4; ++j) {
            float2 v = unpack2(acc[i][j]);
            int col = c0 + 2 * j;
            C1s[(r0 + i) * N1 + col]     = fmaxf(v.x + b1[col], 0.f);
            C1s[(r0 + i) * N1 + col + 1] = fmaxf(v.y + b1[col + 1], 0.f);
        }
    __syncthreads();

    // ---- stage 2: C2 = C1 @ W2 + b2
    unsigned long long acc2[8][2];
    #pragma unroll
    for (int i = 0; i < 8; ++i) { acc2[i][0] = 0ULL; acc2[i][1] = 0ULL; }
    const int c2 = lane * 4;          // cols 0..127

    for (int k0 = 0; k0 < N1; k0 += 64) {
        const float* w2p = W2 + (size_t)k0 * N2;        // 64 contiguous rows
        for (int idx = tid; idx < 64 * N2; idx += 256) Ws2[idx] = w2p[idx];
        __syncthreads();
        #pragma unroll 8
        for (int kk = 0; kk < 64; ++kk) {
            unsigned long long a2[8];
            #pragma unroll
            for (int i = 0; i < 8; ++i) {
                float av = C1s[(r0 + i) * N1 + k0 + kk]; // broadcast
                a2[i] = pack2(av, av);
            }
            float4 w = *(const float4*)(Ws2 + kk * N2 + c2);
            unsigned long long wv0 = pack2(w.x, w.y), wv1 = pack2(w.z, w.w);
            #pragma unroll
            for (int i = 0; i < 8; ++i) {
                fma2(acc2[i][0], a2[i], wv0);
                fma2(acc2[i][1], a2[i], wv1);
            }
        }
        __syncthreads();
    }

    // ---- epilogue: +b2, transpose via padded SMEM, store H[b][z][row]
    float* Tb = C1s;   // reuse, stride 129 (conflict-free transposed read)
    #pragma unroll
    for (int i = 0; i < 8; ++i)
        #pragma unroll
        for (int j = 0; j < 2; ++j) {
            float2 v = unpack2(acc2[i][j]);
            int col = c2 + 2 * j;
            Tb[(r0 + i) * 129 + col]     = v.x + b2[col];
            Tb[(r0 + i) * 129 + col + 1] = v.y + b2[col + 1];
        }
    __syncthreads();
    float* hb = g_H + (size_t)b * N2 * ROWS + row0;
    for (int e = tid; e < TM * N2; e += 256) {
        int z = e >> 6, rr = e & 63;
        hb[(size_t)z * ROWS + rr] = Tb[rr * 129 + z];    // 256B coalesced segments
    }
}

// ============================================================
// Kernel 2: invariant pooling + vector_log.
// CTA per (b,z): 128x128 slice in SMEM (stride 129), thread a owns row a.
// Denominators are constants (pad channel is all-ones).
// ============================================================
__global__ void pool_kernel()
{
    extern __shared__ float S[];       // 128*129 floats
    const int tid = threadIdx.x;       // 128 threads
    const int bz = blockIdx.x;
    const float* src = g_H + (size_t)bz * ROWS;

    for (int e = tid; e < ROWS; e += 128)
        S[(e >> 7) * 129 + (e & 127)] = src[e];
    __syncthreads();

    const int a = tid;
    const float* rowp = S + a * 129;
    float d = rowp[a];
    float r = 0.f, c = 0.f, p4 = 0.f, p5 = 0.f;
    #pragma unroll 4
    for (int bb = 0; bb < 128; ++bb) {
        float xab = rowp[bb];            // stride-129 across threads: conflict-free
        float xba = S[bb * 129 + a];     // stride-1 across threads: conflict-free
        r += xab; c += xba;
        p4 = fmaf(xab, xab, p4);
        p5 = fmaf(xab, xba, p5);
    }
    float vals[8] = { d, r, d * d, d * r, p4, p5, r * r, r * c };
    __syncthreads();                     // done reading S, reuse front for reduction

    float* red = S;                      // [4 warps][8]
    #pragma unroll
    for (int q = 0; q < 8; ++q) {
        float v = vals[q];
        #pragma unroll
        for (int off = 16; off > 0; off >>= 1)
            v += __shfl_down_sync(0xffffffff, v, off);
        if ((tid & 31) == 0) red[(tid >> 5) * 8 + q] = v;
    }
    __syncthreads();
    if (tid < 8) {
        float h = red[tid] + red[8 + tid] + red[16 + tid] + red[24 + tid];
        const float denom[8] = {128.f, 16384.f, 128.f, 16384.f,
                                16384.f, 16384.f, 2097152.f, 2097152.f};
        float p = h / denom[tid];
        float vl = copysignf(log1pf(fabsf(p)) * 0.1f, p);
        int b = bz >> 7, z = bz & 127;
        g_P[b * 1024 + tid * 128 + z] = vl;
    }
}

// ============================================================
// Kernel 3a: H2 = relu(P @ W3 + b3)   [16 x 256]
// ============================================================
__global__ void mlp2a_kernel(const float* __restrict__ W3, const float* __restrict__ b3)
{
    const int tid = threadIdx.x;             // 256
    const int n = blockIdx.x * 16 + (tid & 15);
    const int r = tid >> 4;
    const float* p = g_P + r * 1024;
    float acc = b3[n];
    #pragma unroll 8
    for (int k = 0; k < 1024; ++k)
        acc = fmaf(p[k], W3[k * 256 + n], acc);
    g_H2[r * 256 + n] = fmaxf(acc, 0.f);
}

// ============================================================
// Kernel 3b: out = tanh(H2 @ W4 + b4) * 8   [16 x 2]
// ============================================================
__global__ void mlp2b_kernel(const float* __restrict__ W4, const float* __restrict__ b4,
                             float* __restrict__ out)
{
    const int t = threadIdx.x;  // 32
    const int r = t >> 1, c = t & 1;
    float s = b4[c];
    #pragma unroll 8
    for (int k = 0; k < 256; ++k)
        s = fmaf(g_H2[r * 256 + k], W4[k * 2 + c], s);
    out[t] = tanhf(s) * 8.0f;
}

// ============================================================
extern "C" void kernel_launch(void* const* d_in, const int* in_sizes, int n_in,
                              void* d_out, int out_size)
{
    const float* fgc = (const float*)d_in[0];
    const float* fgt = (const float*)d_in[1];
    const float* bgc = (const float*)d_in[2];
    const float* bgt = (const float*)d_in[3];
    const float* W1  = (const float*)d_in[4];
    const float* b1  = (const float*)d_in[5];
    const float* W2  = (const float*)d_in[6];
    const float* b2  = (const float*)d_in[7];
    const float* W3  = (const float*)d_in[8];
    const float* b3  = (const float*)d_in[9];
    const float* W4  = (const float*)d_in[10];
    const float* b4  = (const float*)d_in[11];
    float* out = (float*)d_out;

    const int SMEM1 = (TM * CHN + CHN * N1 + TM * N1 + 64 * N2) * 4;  // 113664 B
    const int SMEM2 = 128 * 129 * 4;                                  // 66048 B
    cudaFuncSetAttribute(gemm12_kernel, cudaFuncAttributeMaxDynamicSharedMemorySize, SMEM1);
    cudaFuncSetAttribute(pool_kernel,   cudaFuncAttributeMaxDynamicSharedMemorySize, SMEM2);

    gemm12_kernel<<<dim3(ROWS / TM, NB), 256, SMEM1>>>(fgc, fgt, bgc, bgt, W1, b1, W2, b2);
    pool_kernel<<<NB * N2, 128, SMEM2>>>();
    mlp2a_kernel<<<16, 256>>>(W3, b3);
    mlp2b_kernel<<<1, 32>>>(W4, b4, out);
}

// round 4
// speedup vs baseline: 3.1312x; 2.4632x over previous
#include <cuda_runtime.h>
#include <cuda_bf16.h>
#include <math.h>
#include <stdint.h>

#define NB 16
#define ROWS 16384

// ---------------- device scratch ----------------
__device__ float g_H[(size_t)NB * 128 * ROWS];   // [b][z][row]
__device__ float g_P[NB * 1024];
__device__ float g_H2[NB * 256];
__device__ __align__(16) __nv_bfloat16 g_W1h[21 * 256 * 16];  // [c][n][kk]
__device__ __align__(16) __nv_bfloat16 g_W1l[21 * 256 * 16];
__device__ __align__(16) __nv_bfloat16 g_W2h[16 * 128 * 16];  // [c][n][kk]
__device__ __align__(16) __nv_bfloat16 g_W2l[16 * 128 * 16];

// ---------------- smem layout (bytes) ----------------
// C1 (stage1 output as stage2 A operand): 128 rows x 256 k, pitch 264 elems (528B)
#define C1H 0
#define C1L 67584
#define S1  135168
// stage1 buffers: A tile 128x16 (pitch 24 elems = 48B) hi/lo, B tile 256x16 (pitch 48B) hi/lo
#define A1H(bi) (S1 + (bi) * 36864)
#define A1L(bi) (A1H(bi) + 6144)
#define B1H(bi) (A1H(bi) + 12288)
#define B1L(bi) (A1H(bi) + 24576)
// stage2 B tiles reuse the stage1 region
#define B2H(bi) (S1 + (bi) * 12288)
#define B2L(bi) (B2H(bi) + 6144)
#define SMEM_TOTAL 208896

// ---------------- helpers ----------------
__device__ __forceinline__ uint32_t smem_u32(const void* p) {
    uint32_t a;
    asm("{ .reg .u64 t; cvta.to.shared.u64 t, %1; cvt.u32.u64 %0, t; }" : "=r"(a) : "l"(p));
    return a;
}
__device__ __forceinline__ void ldmat4(uint32_t addr, uint32_t r[4]) {
    asm volatile("ldmatrix.sync.aligned.m8n8.x4.shared.b16 {%0,%1,%2,%3}, [%4];"
        : "=r"(r[0]), "=r"(r[1]), "=r"(r[2]), "=r"(r[3]) : "r"(addr) : "memory");
}
__device__ __forceinline__ void mma16816(float d[4], const uint32_t a[4],
                                         uint32_t b0, uint32_t b1) {
    asm volatile("mma.sync.aligned.m16n8k16.row.col.f32.bf16.bf16.f32 "
        "{%0,%1,%2,%3}, {%4,%5,%6,%7}, {%8,%9}, {%0,%1,%2,%3};"
        : "+f"(d[0]), "+f"(d[1]), "+f"(d[2]), "+f"(d[3])
        : "r"(a[0]), "r"(a[1]), "r"(a[2]), "r"(a[3]), "r"(b0), "r"(b1));
}
__device__ __forceinline__ void split1(float x, __nv_bfloat16& h, __nv_bfloat16& l) {
    h = __float2bfloat16(x);
    l = __float2bfloat16(x - __bfloat162float(h));
}
__device__ __forceinline__ void split2(float x, float y, uint32_t& hi, uint32_t& lo) {
    __nv_bfloat16 hx, lx, hy, ly;
    split1(x, hx, lx); split1(y, hy, ly);
    hi = (uint32_t)__bfloat16_as_ushort(hx) | ((uint32_t)__bfloat16_as_ushort(hy) << 16);
    lo = (uint32_t)__bfloat16_as_ushort(lx) | ((uint32_t)__bfloat16_as_ushort(ly) << 16);
}
__device__ __forceinline__ const float* selsrc(int s, const float* a, const float* b,
                                               const float* c, const float* d) {
    return s == 0 ? a : (s == 1 ? b : (s == 2 ? c : d));
}

// ============================================================
// prep: split W1/W2 into bf16 hi/lo, pre-chunked [c][n][kk]
// ============================================================
__global__ void prep_w_kernel(const float* __restrict__ W1, const float* __restrict__ W2)
{
    int idx = blockIdx.x * 256 + threadIdx.x;
    if (idx < 21 * 4096) {
        int c = idx >> 12, rem = idx & 4095;
        int n = rem >> 4, kk = rem & 15;
        int k = c * 16 + kk;
        float w = (k < 324) ? W1[k * 256 + n] : 0.f;
        __nv_bfloat16 h, l; split1(w, h, l);
        g_W1h[idx] = h; g_W1l[idx] = l;
    } else {
        int j = idx - 21 * 4096;
        if (j < 16 * 2048) {
            int c = j >> 11, rem = j & 2047;
            int n = rem >> 4, kk = rem & 15;
            int k = c * 16 + kk;
            float w = W2[k * 128 + n];
            __nv_bfloat16 h, l; split1(w, h, l);
            g_W2h[j] = h; g_W2l[j] = l;
        }
    }
}

// ============================================================
// fused GEMM1 -> ReLU -> GEMM2 via mma.sync bf16 split-precision
// CTA: 512 threads (16 warps), 128 rows. grid (128, 16).
// ============================================================
__global__ void __launch_bounds__(512, 1) gemm_mma_kernel(
    const float* __restrict__ fgc, const float* __restrict__ fgt,
    const float* __restrict__ bgc, const float* __restrict__ bgt,
    const float* __restrict__ b1, const float* __restrict__ b2)
{
    extern __shared__ char sm[];
    const uint32_t smb = smem_u32(sm);
    const int tid = threadIdx.x, lane = tid & 31, warp = tid >> 5;
    const int wm = warp & 3, wn = warp >> 2;
    const int b = blockIdx.y;
    const int row0 = blockIdx.x * 128;
    const int g = lane >> 2, tg = lane & 3;

    // gather mapping: thread -> (row gr, kk = gk0 + 4q)
    const int gr = tid & 127;
    const int gk0 = tid >> 7;
    const int R = row0 + gr;

    float acc[2][8][4];
    #pragma unroll
    for (int i = 0; i < 2; ++i)
        #pragma unroll
        for (int j = 0; j < 8; ++j)
            #pragma unroll
            for (int r = 0; r < 4; ++r) acc[i][j][r] = 0.f;

    // ---- prologue: fill stage1 buf 0 (chunk 0) ----
    {
        #pragma unroll
        for (int q = 0; q < 4; ++q) {
            int k = gk0 + q * 4;                    // all < 324
            int t = k / 12, rem = k - t * 12, s = rem / 3, cm = rem - s * 3;
            const float* sp = selsrc(s, fgc, fgt, bgc, bgt);
            float v = sp[((size_t)(b * 27 + t) * ROWS + R) * 3 + cm];
            __nv_bfloat16 h, l; split1(v, h, l);
            *(__nv_bfloat16*)(sm + A1H(0) + gr * 48 + (gk0 + q * 4) * 2) = h;
            *(__nv_bfloat16*)(sm + A1L(0) + gr * 48 + (gk0 + q * 4) * 2) = l;
        }
        int n = tid >> 1, half = tid & 1;
        uint4 vh = ((const uint4*)(g_W1h))[tid];
        uint4 vl = ((const uint4*)(g_W1l))[tid];
        *(uint4*)(sm + B1H(0) + n * 48 + half * 16) = vh;
        *(uint4*)(sm + B1L(0) + n * 48 + half * 16) = vl;
    }
    __syncthreads();

    // ---- stage 1 main loop: 21 chunks of k16 ----
    for (int c = 0; c < 21; ++c) {
        const int bi = c & 1;
        const bool hn = (c < 20);
        float av[4];
        uint4 wh, wl;
        if (hn) {
            const int cn = c + 1;
            #pragma unroll
            for (int q = 0; q < 4; ++q) {
                int k = cn * 16 + gk0 + q * 4;
                float v = 0.f;
                if (k < 324) {
                    int t = k / 12, rem = k - t * 12, s = rem / 3, cm = rem - s * 3;
                    const float* sp = selsrc(s, fgc, fgt, bgc, bgt);
                    v = sp[((size_t)(b * 27 + t) * ROWS + R) * 3 + cm];
                }
                av[q] = v;
            }
            wh = ((const uint4*)(g_W1h + cn * 4096))[tid];
            wl = ((const uint4*)(g_W1l + cn * 4096))[tid];
        }

        // compute chunk c
        uint32_t ah[2][4], al[2][4];
        {
            uint32_t aAddr = smb + A1H(bi)
                + (uint32_t)((wm * 32 + (lane & 15)) * 48 + (lane >> 4) * 16);
            ldmat4(aAddr, ah[0]);
            ldmat4(aAddr + 16 * 48, ah[1]);
            ldmat4(aAddr + 6144, al[0]);
            ldmat4(aAddr + 6144 + 16 * 48, al[1]);
        }
        uint32_t bAddr = smb + B1H(bi)
            + (uint32_t)((wn * 64 + (lane & 15)) * 48 + (lane >> 4) * 16);
        #pragma unroll
        for (int jj = 0; jj < 4; ++jj) {
            uint32_t bh[4], bl[4];
            ldmat4(bAddr + jj * 16 * 48, bh);
            ldmat4(bAddr + jj * 16 * 48 + 12288, bl);
            #pragma unroll
            for (int i = 0; i < 2; ++i) {
                #pragma unroll
                for (int jn = 0; jn < 2; ++jn) {
                    int j = jj * 2 + jn;
                    mma16816(acc[i][j], ah[i], bh[jn], bh[jn + 2]);
                    mma16816(acc[i][j], ah[i], bl[jn], bl[jn + 2]);
                    mma16816(acc[i][j], al[i], bh[jn], bh[jn + 2]);
                }
            }
        }

        if (hn) {
            const int nbi = bi ^ 1;
            #pragma unroll
            for (int q = 0; q < 4; ++q) {
                __nv_bfloat16 h, l; split1(av[q], h, l);
                *(__nv_bfloat16*)(sm + A1H(nbi) + gr * 48 + (gk0 + q * 4) * 2) = h;
                *(__nv_bfloat16*)(sm + A1L(nbi) + gr * 48 + (gk0 + q * 4) * 2) = l;
            }
            int n = tid >> 1, half = tid & 1;
            *(uint4*)(sm + B1H(nbi) + n * 48 + half * 16) = wh;
            *(uint4*)(sm + B1L(nbi) + n * 48 + half * 16) = wl;
        }
        __syncthreads();
    }

    // ---- epilogue 1: bias + relu + split -> C1 smem (pitch 528B) ----
    #pragma unroll
    for (int i = 0; i < 2; ++i) {
        int m0 = wm * 32 + i * 16 + g;
        #pragma unroll
        for (int j = 0; j < 8; ++j) {
            int n = wn * 64 + j * 8 + tg * 2;
            float bn0 = b1[n], bn1 = b1[n + 1];
            float x0 = fmaxf(acc[i][j][0] + bn0, 0.f);
            float x1 = fmaxf(acc[i][j][1] + bn1, 0.f);
            float x2 = fmaxf(acc[i][j][2] + bn0, 0.f);
            float x3 = fmaxf(acc[i][j][3] + bn1, 0.f);
            uint32_t hi, lo;
            split2(x0, x1, hi, lo);
            *(uint32_t*)(sm + C1H + m0 * 528 + n * 2) = hi;
            *(uint32_t*)(sm + C1L + m0 * 528 + n * 2) = lo;
            split2(x2, x3, hi, lo);
            *(uint32_t*)(sm + C1H + (m0 + 8) * 528 + n * 2) = hi;
            *(uint32_t*)(sm + C1L + (m0 + 8) * 528 + n * 2) = lo;
        }
    }
    __syncthreads();

    // ---- stage 2: C2 = C1 @ W2, K=256 (16 chunks) ----
    float acc2[2][4][4];
    #pragma unroll
    for (int i = 0; i < 2; ++i)
        #pragma unroll
        for (int j = 0; j < 4; ++j)
            #pragma unroll
            for (int r = 0; r < 4; ++r) acc2[i][j][r] = 0.f;

    {   // prologue: W2 chunk 0
        int e = tid & 255, n = e >> 1, half = e & 1;
        const __nv_bfloat16* src = (tid < 256) ? g_W2h : g_W2l;
        uint4 v = ((const uint4*)(src))[e];
        *(uint4*)(sm + ((tid < 256) ? B2H(0) : B2L(0)) + n * 48 + half * 16) = v;
    }
    __syncthreads();

    for (int c = 0; c < 16; ++c) {
        const int bi = c & 1;
        const bool hn = (c < 15);
        uint4 wv;
        if (hn) {
            int e = tid & 255;
            const __nv_bfloat16* src = (tid < 256) ? g_W2h : g_W2l;
            wv = ((const uint4*)(src + (c + 1) * 2048))[e];
        }

        uint32_t ah[2][4], al[2][4];
        {
            uint32_t aAddr = smb + C1H
                + (uint32_t)((wm * 32 + (lane & 15)) * 528 + c * 32 + (lane >> 4) * 16);
            ldmat4(aAddr, ah[0]);
            ldmat4(aAddr + 16 * 528, ah[1]);
            ldmat4(aAddr + C1L, al[0]);
            ldmat4(aAddr + C1L + 16 * 528, al[1]);
        }
        uint32_t bAddr = smb + B2H(bi)
            + (uint32_t)((wn * 32 + (lane & 15)) * 48 + (lane >> 4) * 16);
        #pragma unroll
        for (int jj = 0; jj < 2; ++jj) {
            uint32_t bh[4], bl[4];
            ldmat4(bAddr + jj * 16 * 48, bh);
            ldmat4(bAddr + jj * 16 * 48 + 6144, bl);
            #pragma unroll
            for (int i = 0; i < 2; ++i) {
                #pragma unroll
                for (int jn = 0; jn < 2; ++jn) {
                    int j = jj * 2 + jn;
                    mma16816(acc2[i][j], ah[i], bh[jn], bh[jn + 2]);
                    mma16816(acc2[i][j], ah[i], bl[jn], bl[jn + 2]);
                    mma16816(acc2[i][j], al[i], bh[jn], bh[jn + 2]);
                }
            }
        }

        if (hn) {
            int e = tid & 255, n = e >> 1, half = e & 1;
            *(uint4*)(sm + ((tid < 256) ? B2H(bi ^ 1) : B2L(bi ^ 1)) + n * 48 + half * 16) = wv;
        }
        __syncthreads();
    }

    // ---- epilogue 2: + b2, write g_H[b][z][row0 + m] ----
    #pragma unroll
    for (int i = 0; i < 2; ++i) {
        int m0 = wm * 32 + i * 16 + g;
        #pragma unroll
        for (int j = 0; j < 4; ++j) {
            int z = wn * 32 + j * 8 + tg * 2;
            float bz0 = b2[z], bz1 = b2[z + 1];
            float* d0 = g_H + ((size_t)b * 128 + z) * ROWS + row0;
            float* d1 = g_H + ((size_t)b * 128 + z + 1) * ROWS + row0;
            d0[m0]     = acc2[i][j][0] + bz0;
            d1[m0]     = acc2[i][j][1] + bz1;
            d0[m0 + 8] = acc2[i][j][2] + bz0;
            d1[m0 + 8] = acc2[i][j][3] + bz1;
        }
    }
}

// ============================================================
// invariant pooling + vector_log (CTA per (b,z))
// ============================================================
__global__ void pool_kernel()
{
    extern __shared__ float S[];
    const int tid = threadIdx.x;
    const int bz = blockIdx.x;
    const float* src = g_H + (size_t)bz * ROWS;
    for (int e = tid; e < ROWS; e += 128)
        S[(e >> 7) * 129 + (e & 127)] = src[e];
    __syncthreads();
    const int a = tid;
    const float* rowp = S + a * 129;
    float d = rowp[a], r = 0.f, c = 0.f, p4 = 0.f, p5 = 0.f;
    #pragma unroll 4
    for (int bb = 0; bb < 128; ++bb) {
        float xab = rowp[bb], xba = S[bb * 129 + a];
        r += xab; c += xba;
        p4 = fmaf(xab, xab, p4);
        p5 = fmaf(xab, xba, p5);
    }
    float vals[8] = { d, r, d * d, d * r, p4, p5, r * r, r * c };
    __syncthreads();
    float* red = S;
    #pragma unroll
    for (int q = 0; q < 8; ++q) {
        float v = vals[q];
        #pragma unroll
        for (int off = 16; off > 0; off >>= 1)
            v += __shfl_down_sync(0xffffffff, v, off);
        if ((tid & 31) == 0) red[(tid >> 5) * 8 + q] = v;
    }
    __syncthreads();
    if (tid < 8) {
        float h = red[tid] + red[8 + tid] + red[16 + tid] + red[24 + tid];
        const float denom[8] = {128.f, 16384.f, 128.f, 16384.f,
                                16384.f, 16384.f, 2097152.f, 2097152.f};
        float p = h / denom[tid];
        float vl = copysignf(log1pf(fabsf(p)) * 0.1f, p);
        g_P[(bz >> 7) * 1024 + tid * 128 + (bz & 127)] = vl;
    }
}

// ============================================================
__global__ void mlp2a_kernel(const float* __restrict__ W3, const float* __restrict__ b3)
{
    __shared__ float part[256];
    const int r = blockIdx.x;
    const int n = threadIdx.x & 255, h = threadIdx.x >> 8;
    const float* p = g_P + r * 1024 + h * 512;
    const float* w = W3 + (size_t)h * 512 * 256;
    float acc = 0.f;
    #pragma unroll 8
    for (int k = 0; k < 512; ++k)
        acc = fmaf(p[k], w[k * 256 + n], acc);
    if (h) part[n] = acc;
    __syncthreads();
    if (!h) g_H2[r * 256 + n] = fmaxf(acc + part[n] + b3[n], 0.f);
}

__global__ void mlp2b_kernel(const float* __restrict__ W4, const float* __restrict__ b4,
                             float* __restrict__ out)
{
    const int t = threadIdx.x;            // 256
    const int o = t >> 3, g = t & 7;
    const int r = o >> 1, c = o & 1;
    float s = 0.f;
    #pragma unroll 8
    for (int k = g; k < 256; k += 8)
        s = fmaf(g_H2[r * 256 + k], W4[k * 2 + c], s);
    s += __shfl_down_sync(0xffffffff, s, 4, 8);
    s += __shfl_down_sync(0xffffffff, s, 2, 8);
    s += __shfl_down_sync(0xffffffff, s, 1, 8);
    if (g == 0) out[o] = tanhf(s + b4[c]) * 8.0f;
}

// ============================================================
extern "C" void kernel_launch(void* const* d_in, const int* in_sizes, int n_in,
                              void* d_out, int out_size)
{
    const float* fgc = (const float*)d_in[0];
    const float* fgt = (const float*)d_in[1];
    const float* bgc = (const float*)d_in[2];
    const float* bgt = (const float*)d_in[3];
    const float* W1  = (const float*)d_in[4];
    const float* b1  = (const float*)d_in[5];
    const float* W2  = (const float*)d_in[6];
    const float* b2  = (const float*)d_in[7];
    const float* W3  = (const float*)d_in[8];
    const float* b3  = (const float*)d_in[9];
    const float* W4  = (const float*)d_in[10];
    const float* b4  = (const float*)d_in[11];
    float* out = (float*)d_out;

    cudaFuncSetAttribute(gemm_mma_kernel, cudaFuncAttributeMaxDynamicSharedMemorySize, SMEM_TOTAL);
    cudaFuncSetAttribute(pool_kernel,     cudaFuncAttributeMaxDynamicSharedMemorySize, 128 * 129 * 4);

    prep_w_kernel<<<464, 256>>>(W1, W2);
    gemm_mma_kernel<<<dim3(128, NB), 512, SMEM_TOTAL>>>(fgc, fgt, bgc, bgt, b1, b2);
    pool_kernel<<<NB * 128, 128, 128 * 129 * 4>>>();
    mlp2a_kernel<<<NB, 512>>>(W3, b3);
    mlp2b_kernel<<<1, 256>>>(W4, b4, out);
}

// round 5
// speedup vs baseline: 4.0715x; 1.3003x over previous
#include <cuda_runtime.h>
#include <cuda_fp16.h>
#include <math.h>
#include <stdint.h>

#define NB 16
#define ROWS 16384

// ---------------- device scratch ----------------
__device__ float g_H[(size_t)NB * 128 * ROWS];   // [b][z][row]
__device__ float g_P[NB * 1024];
__device__ float g_part[NB * 8 * 256];
__device__ __align__(16) __half g_W1f[21 * 256 * 16];  // [c][n][kk] fp16
__device__ __align__(16) __half g_W2f[16 * 128 * 16];  // [c][n][kk] fp16

// ---------------- smem layout (bytes) ----------------
#define C1H 0
#define C1L 67584
#define S1  135168
#define A1H(bi) (S1 + (bi) * 24576)
#define A1L(bi) (A1H(bi) + 6144)
#define B1F(bi) (A1H(bi) + 12288)
#define B2F(bi) (S1 + (bi) * 6144)
#define SMEM_TOTAL 184320

// ---------------- helpers ----------------
__device__ __forceinline__ uint32_t smem_u32(const void* p) {
    uint32_t a;
    asm("{ .reg .u64 t; cvta.to.shared.u64 t, %1; cvt.u32.u64 %0, t; }" : "=r"(a) : "l"(p));
    return a;
}
__device__ __forceinline__ void ldmat4(uint32_t addr, uint32_t r[4]) {
    asm volatile("ldmatrix.sync.aligned.m8n8.x4.shared.b16 {%0,%1,%2,%3}, [%4];"
        : "=r"(r[0]), "=r"(r[1]), "=r"(r[2]), "=r"(r[3]) : "r"(addr) : "memory");
}
__device__ __forceinline__ void mma16816(float d[4], const uint32_t a[4],
                                         uint32_t b0, uint32_t b1) {
    asm volatile("mma.sync.aligned.m16n8k16.row.col.f32.f16.f16.f32 "
        "{%0,%1,%2,%3}, {%4,%5,%6,%7}, {%8,%9}, {%0,%1,%2,%3};"
        : "+f"(d[0]), "+f"(d[1]), "+f"(d[2]), "+f"(d[3])
        : "r"(a[0]), "r"(a[1]), "r"(a[2]), "r"(a[3]), "r"(b0), "r"(b1));
}
__device__ __forceinline__ void split1(float x, __half& h, __half& l) {
    h = __float2half_rn(x);
    l = __float2half_rn(x - __half2float(h));
}
__device__ __forceinline__ void split2(float x, float y, uint32_t& hi, uint32_t& lo) {
    __half hx, lx, hy, ly;
    split1(x, hx, lx); split1(y, hy, ly);
    hi = (uint32_t)__half_as_ushort(hx) | ((uint32_t)__half_as_ushort(hy) << 16);
    lo = (uint32_t)__half_as_ushort(lx) | ((uint32_t)__half_as_ushort(ly) << 16);
}
__device__ __forceinline__ const float* selsrc(int s, const float* a, const float* b,
                                               const float* c, const float* d) {
    return s == 0 ? a : (s == 1 ? b : (s == 2 ? c : d));
}

// ============================================================
// prep: W1/W2 -> fp16, pre-chunked [c][n][kk]
// ============================================================
__global__ void prep_w_kernel(const float* __restrict__ W1, const float* __restrict__ W2)
{
    int idx = blockIdx.x * 256 + threadIdx.x;
    if (idx < 21 * 4096) {
        int c = idx >> 12, rem = idx & 4095;
        int n = rem >> 4, kk = rem & 15;
        int k = c * 16 + kk;
        g_W1f[idx] = __float2half_rn((k < 324) ? W1[k * 256 + n] : 0.f);
    } else {
        int j = idx - 21 * 4096;
        if (j < 16 * 2048) {
            int c = j >> 11, rem = j & 2047;
            int n = rem >> 4, kk = rem & 15;
            int k = c * 16 + kk;
            g_W2f[j] = __float2half_rn(W2[k * 128 + n]);
        }
    }
}

// ============================================================
// fused GEMM1 -> ReLU -> GEMM2, fp16 2-MMA split (activations split, weights single)
// ============================================================
__global__ void __launch_bounds__(512, 1) gemm_mma_kernel(
    const float* __restrict__ fgc, const float* __restrict__ fgt,
    const float* __restrict__ bgc, const float* __restrict__ bgt,
    const float* __restrict__ b1, const float* __restrict__ b2)
{
    extern __shared__ char sm[];
    const uint32_t smb = smem_u32(sm);
    const int tid = threadIdx.x, lane = tid & 31, warp = tid >> 5;
    const int wm = warp & 3, wn = warp >> 2;
    const int b = blockIdx.y;
    const int row0 = blockIdx.x * 128;
    const int g = lane >> 2, tg = lane & 3;

    const int gr = tid & 127;
    const int gk0 = tid >> 7;
    const int R = row0 + gr;

    float acc[2][8][4];
    #pragma unroll
    for (int i = 0; i < 2; ++i)
        #pragma unroll
        for (int j = 0; j < 8; ++j)
            #pragma unroll
            for (int r = 0; r < 4; ++r) acc[i][j][r] = 0.f;

    // ---- prologue: fill stage1 buf 0 ----
    {
        #pragma unroll
        for (int q = 0; q < 4; ++q) {
            int k = gk0 + q * 4;
            int t = k / 12, rem = k - t * 12, s = rem / 3, cm = rem - s * 3;
            const float* sp = selsrc(s, fgc, fgt, bgc, bgt);
            float v = sp[((size_t)(b * 27 + t) * ROWS + R) * 3 + cm];
            __half h, l; split1(v, h, l);
            *(__half*)(sm + A1H(0) + gr * 48 + k * 2) = h;
            *(__half*)(sm + A1L(0) + gr * 48 + k * 2) = l;
        }
        int n = tid >> 1, half = tid & 1;
        uint4 vh = ((const uint4*)(g_W1f))[tid];
        *(uint4*)(sm + B1F(0) + n * 48 + half * 16) = vh;
    }
    __syncthreads();

    // ---- stage 1: 21 chunks of k16 ----
    for (int c = 0; c < 21; ++c) {
        const int bi = c & 1;
        const bool hn = (c < 20);
        float av[4];
        uint4 wh;
        if (hn) {
            const int cn = c + 1;
            #pragma unroll
            for (int q = 0; q < 4; ++q) {
                int k = cn * 16 + gk0 + q * 4;
                float v = 0.f;
                if (k < 324) {
                    int t = k / 12, rem = k - t * 12, s = rem / 3, cm = rem - s * 3;
                    const float* sp = selsrc(s, fgc, fgt, bgc, bgt);
                    v = sp[((size_t)(b * 27 + t) * ROWS + R) * 3 + cm];
                }
                av[q] = v;
            }
            wh = ((const uint4*)(g_W1f + cn * 4096))[tid];
        }

        uint32_t ah[2][4], al[2][4];
        {
            uint32_t aAddr = smb + A1H(bi)
                + (uint32_t)((wm * 32 + (lane & 15)) * 48 + (lane >> 4) * 16);
            ldmat4(aAddr, ah[0]);
            ldmat4(aAddr + 16 * 48, ah[1]);
            ldmat4(aAddr + 6144, al[0]);
            ldmat4(aAddr + 6144 + 16 * 48, al[1]);
        }
        uint32_t bAddr = smb + B1F(bi)
            + (uint32_t)((wn * 64 + (lane & 15)) * 48 + (lane >> 4) * 16);
        #pragma unroll
        for (int jj = 0; jj < 4; ++jj) {
            uint32_t bh[4];
            ldmat4(bAddr + jj * 16 * 48, bh);
            #pragma unroll
            for (int i = 0; i < 2; ++i) {
                #pragma unroll
                for (int jn = 0; jn < 2; ++jn) {
                    int j = jj * 2 + jn;
                    mma16816(acc[i][j], ah[i], bh[jn], bh[jn + 2]);
                    mma16816(acc[i][j], al[i], bh[jn], bh[jn + 2]);
                }
            }
        }

        if (hn) {
            const int nbi = bi ^ 1;
            #pragma unroll
            for (int q = 0; q < 4; ++q) {
                int k = gk0 + q * 4;
                __half h, l; split1(av[q], h, l);
                *(__half*)(sm + A1H(nbi) + gr * 48 + k * 2) = h;
                *(__half*)(sm + A1L(nbi) + gr * 48 + k * 2) = l;
            }
            int n = tid >> 1, half = tid & 1;
            *(uint4*)(sm + B1F(nbi) + n * 48 + half * 16) = wh;
        }
        __syncthreads();
    }

    // ---- epilogue 1: bias + relu + fp16 split -> C1 smem ----
    #pragma unroll
    for (int i = 0; i < 2; ++i) {
        int m0 = wm * 32 + i * 16 + g;
        #pragma unroll
        for (int j = 0; j < 8; ++j) {
            int n = wn * 64 + j * 8 + tg * 2;
            float bn0 = b1[n], bn1 = b1[n + 1];
            float x0 = fmaxf(acc[i][j][0] + bn0, 0.f);
            float x1 = fmaxf(acc[i][j][1] + bn1, 0.f);
            float x2 = fmaxf(acc[i][j][2] + bn0, 0.f);
            float x3 = fmaxf(acc[i][j][3] + bn1, 0.f);
            uint32_t hi, lo;
            split2(x0, x1, hi, lo);
            *(uint32_t*)(sm + C1H + m0 * 528 + n * 2) = hi;
            *(uint32_t*)(sm + C1L + m0 * 528 + n * 2) = lo;
            split2(x2, x3, hi, lo);
            *(uint32_t*)(sm + C1H + (m0 + 8) * 528 + n * 2) = hi;
            *(uint32_t*)(sm + C1L + (m0 + 8) * 528 + n * 2) = lo;
        }
    }
    __syncthreads();

    // ---- stage 2: C2 = C1 @ W2, K=256 (16 chunks) ----
    float acc2[2][4][4];
    #pragma unroll
    for (int i = 0; i < 2; ++i)
        #pragma unroll
        for (int j = 0; j < 4; ++j)
            #pragma unroll
            for (int r = 0; r < 4; ++r) acc2[i][j][r] = 0.f;

    if (tid < 256) {   // prologue: W2 chunk 0 (4 KB)
        int n = tid >> 1, half = tid & 1;
        uint4 v = ((const uint4*)(g_W2f))[tid];
        *(uint4*)(sm + B2F(0) + n * 48 + half * 16) = v;
    }
    __syncthreads();

    for (int c = 0; c < 16; ++c) {
        const int bi = c & 1;
        const bool hn = (c < 15);
        uint4 wv;
        if (hn && tid < 256)
            wv = ((const uint4*)(g_W2f + (c + 1) * 2048))[tid];

        uint32_t ah[2][4], al[2][4];
        {
            uint32_t aAddr = smb + C1H
                + (uint32_t)((wm * 32 + (lane & 15)) * 528 + c * 32 + (lane >> 4) * 16);
            ldmat4(aAddr, ah[0]);
            ldmat4(aAddr + 16 * 528, ah[1]);
            ldmat4(aAddr + C1L, al[0]);
            ldmat4(aAddr + C1L + 16 * 528, al[1]);
        }
        uint32_t bAddr = smb + B2F(bi)
            + (uint32_t)((wn * 32 + (lane & 15)) * 48 + (lane >> 4) * 16);
        #pragma unroll
        for (int jj = 0; jj < 2; ++jj) {
            uint32_t bh[4];
            ldmat4(bAddr + jj * 16 * 48, bh);
            #pragma unroll
            for (int i = 0; i < 2; ++i) {
                #pragma unroll
                for (int jn = 0; jn < 2; ++jn) {
                    int j = jj * 2 + jn;
                    mma16816(acc2[i][j], ah[i], bh[jn], bh[jn + 2]);
                    mma16816(acc2[i][j], al[i], bh[jn], bh[jn + 2]);
                }
            }
        }

        if (hn && tid < 256) {
            int n = tid >> 1, half = tid & 1;
            *(uint4*)(sm + B2F(bi ^ 1) + n * 48 + half * 16) = wv;
        }
        __syncthreads();
    }

    // ---- epilogue 2: + b2, write g_H[b][z][row0 + m] ----
    #pragma unroll
    for (int i = 0; i < 2; ++i) {
        int m0 = wm * 32 + i * 16 + g;
        #pragma unroll
        for (int j = 0; j < 4; ++j) {
            int z = wn * 32 + j * 8 + tg * 2;
            float bz0 = b2[z], bz1 = b2[z + 1];
            float* d0 = g_H + ((size_t)b * 128 + z) * ROWS + row0;
            float* d1 = g_H + ((size_t)b * 128 + z + 1) * ROWS + row0;
            d0[m0]     = acc2[i][j][0] + bz0;
            d1[m0]     = acc2[i][j][1] + bz1;
            d0[m0 + 8] = acc2[i][j][2] + bz0;
            d1[m0 + 8] = acc2[i][j][3] + bz1;
        }
    }
}

// ============================================================
// invariant pooling + vector_log (CTA per (b,z))
// ============================================================
__global__ void pool_kernel()
{
    extern __shared__ float S[];
    const int tid = threadIdx.x;
    const int bz = blockIdx.x;
    const float* src = g_H + (size_t)bz * ROWS;
    for (int e = tid; e < ROWS; e += 128)
        S[(e >> 7) * 129 + (e & 127)] = src[e];
    __syncthreads();
    const int a = tid;
    const float* rowp = S + a * 129;
    float d = rowp[a], r = 0.f, c = 0.f, p4 = 0.f, p5 = 0.f;
    #pragma unroll 4
    for (int bb = 0; bb < 128; ++bb) {
        float xab = rowp[bb], xba = S[bb * 129 + a];
        r += xab; c += xba;
        p4 = fmaf(xab, xab, p4);
        p5 = fmaf(xab, xba, p5);
    }
    float vals[8] = { d, r, d * d, d * r, p4, p5, r * r, r * c };
    __syncthreads();
    float* red = S;
    #pragma unroll
    for (int q = 0; q < 8; ++q) {
        float v = vals[q];
        #pragma unroll
        for (int off = 16; off > 0; off >>= 1)
            v += __shfl_down_sync(0xffffffff, v, off);
        if ((tid & 31) == 0) red[(tid >> 5) * 8 + q] = v;
    }
    __syncthreads();
    if (tid < 8) {
        float h = red[tid] + red[8 + tid] + red[16 + tid] + red[24 + tid];
        const float denom[8] = {128.f, 16384.f, 128.f, 16384.f,
                                16384.f, 16384.f, 2097152.f, 2097152.f};
        float p = h / denom[tid];
        float vl = copysignf(log1pf(fabsf(p)) * 0.1f, p);
        g_P[(bz >> 7) * 1024 + tid * 128 + (bz & 127)] = vl;
    }
}

// ============================================================
// mlp2a: split-K partials (grid 16 x 8)
// ============================================================
__global__ void mlp2a_kernel(const float* __restrict__ W3)
{
    const int r = blockIdx.x, h = blockIdx.y;
    const int n = threadIdx.x;               // 256
    const float* p = g_P + r * 1024 + h * 128;
    const float* w = W3 + (size_t)h * 128 * 256;
    float acc = 0.f;
    #pragma unroll 8
    for (int k = 0; k < 128; ++k)
        acc = fmaf(p[k], w[k * 256 + n], acc);
    g_part[(r * 8 + h) * 256 + n] = acc;
}

// ============================================================
// mlp2b: reduce partials + bias/relu + final GEMV + tanh
// ============================================================
__global__ void mlp2b_kernel(const float* __restrict__ b3,
                             const float* __restrict__ W4, const float* __restrict__ b4,
                             float* __restrict__ out)
{
    __shared__ float H2[16 * 256];
    const int tid = threadIdx.x;              // 512
    for (int e = tid; e < 4096; e += 512) {
        int r = e >> 8, n = e & 255;
        float s = 0.f;
        #pragma unroll
        for (int h = 0; h < 8; ++h) s += g_part[(r * 8 + h) * 256 + n];
        H2[e] = fmaxf(s + b3[n], 0.f);
    }
    __syncthreads();
    const int o = tid >> 4, g = tid & 15;     // 32 outputs x 16-way
    const int r = o >> 1, c = o & 1;
    float s = 0.f;
    #pragma unroll 4
    for (int k = g; k < 256; k += 16)
        s = fmaf(H2[r * 256 + k], W4[k * 2 + c], s);
    s += __shfl_down_sync(0xffffffff, s, 8, 16);
    s += __shfl_down_sync(0xffffffff, s, 4, 16);
    s += __shfl_down_sync(0xffffffff, s, 2, 16);
    s += __shfl_down_sync(0xffffffff, s, 1, 16);
    if (g == 0) out[o] = tanhf(s + b4[c]) * 8.0f;
}

// ============================================================
extern "C" void kernel_launch(void* const* d_in, const int* in_sizes, int n_in,
                              void* d_out, int out_size)
{
    const float* fgc = (const float*)d_in[0];
    const float* fgt = (const float*)d_in[1];
    const float* bgc = (const float*)d_in[2];
    const float* bgt = (const float*)d_in[3];
    const float* W1  = (const float*)d_in[4];
    const float* b1  = (const float*)d_in[5];
    const float* W2  = (const float*)d_in[6];
    const float* b2  = (const float*)d_in[7];
    const float* W3  = (const float*)d_in[8];
    const float* b3  = (const float*)d_in[9];
    const float* W4  = (const float*)d_in[10];
    const float* b4  = (const float*)d_in[11];
    float* out = (float*)d_out;

    cudaFuncSetAttribute(gemm_mma_kernel, cudaFuncAttributeMaxDynamicSharedMemorySize, SMEM_TOTAL);
    cudaFuncSetAttribute(pool_kernel,     cudaFuncAttributeMaxDynamicSharedMemorySize, 128 * 129 * 4);

    prep_w_kernel<<<464, 256>>>(W1, W2);
    gemm_mma_kernel<<<dim3(128, NB), 512, SMEM_TOTAL>>>(fgc, fgt, bgc, bgt, b1, b2);
    pool_kernel<<<NB * 128, 128, 128 * 129 * 4>>>();
    mlp2a_kernel<<<dim3(16, 8), 256>>>(W3);
    mlp2b_kernel<<<1, 512>>>(b3, W4, b4, out);
}

// round 6
// speedup vs baseline: 5.6646x; 1.3913x over previous
#include <cuda_runtime.h>
#include <cuda_fp16.h>
#include <math.h>
#include <stdint.h>

#define NB 16
#define ROWS 16384

// ---------------- device scratch ----------------
__device__ __align__(16) __half g_Hh[(size_t)NB * 128 * ROWS];  // [b][z][row] fp16, 64 MB
__device__ float g_P[NB * 1024];
__device__ float g_part[NB * 16 * 256];
__device__ __align__(16) __half g_W1f[21 * 256 * 16];  // [c][n][kk]
__device__ __align__(16) __half g_W2f[16 * 128 * 16];  // [c][n][kk]

// ---------------- smem layout (bytes) ----------------
#define C1H 0                        // 128 x 264 halves (pitch 528B) = 67584
#define S1  67584
#define A1F(bi) (S1 + (bi) * 18432)  // A tile 128x16 half, pitch 48B = 6144
#define B1F(bi) (A1F(bi) + 6144)     // B tile 256x16 half, pitch 48B = 12288
#define STG 67584                    // epilogue-2 staging: 128 x 272B = 34816 (reuses S1 region)
#define B2F(bi) (104448 + (bi) * 6144)
#define SMEM_TOTAL 116736

// ---------------- helpers ----------------
__device__ __forceinline__ uint32_t smem_u32(const void* p) {
    uint32_t a;
    asm("{ .reg .u64 t; cvta.to.shared.u64 t, %1; cvt.u32.u64 %0, t; }" : "=r"(a) : "l"(p));
    return a;
}
__device__ __forceinline__ void ldmat4(uint32_t addr, uint32_t r[4]) {
    asm volatile("ldmatrix.sync.aligned.m8n8.x4.shared.b16 {%0,%1,%2,%3}, [%4];"
        : "=r"(r[0]), "=r"(r[1]), "=r"(r[2]), "=r"(r[3]) : "r"(addr) : "memory");
}
__device__ __forceinline__ void mma16816(float d[4], const uint32_t a[4],
                                         uint32_t b0, uint32_t b1) {
    asm volatile("mma.sync.aligned.m16n8k16.row.col.f32.f16.f16.f32 "
        "{%0,%1,%2,%3}, {%4,%5,%6,%7}, {%8,%9}, {%0,%1,%2,%3};"
        : "+f"(d[0]), "+f"(d[1]), "+f"(d[2]), "+f"(d[3])
        : "r"(a[0]), "r"(a[1]), "r"(a[2]), "r"(a[3]), "r"(b0), "r"(b1));
}
__device__ __forceinline__ uint32_t packh2(float x, float y) {
    __half2 h = __floats2half2_rn(x, y);
    return *(uint32_t*)&h;
}
__device__ __forceinline__ const float* selsrc(int s, const float* a, const float* b,
                                               const float* c, const float* d) {
    return s == 0 ? a : (s == 1 ? b : (s == 2 ? c : d));
}

// ============================================================
// prep: W1/W2 -> fp16, pre-chunked [c][n][kk]
// ============================================================
__global__ void prep_w_kernel(const float* __restrict__ W1, const float* __restrict__ W2)
{
    int idx = blockIdx.x * 256 + threadIdx.x;
    if (idx < 21 * 4096) {
        int c = idx >> 12, rem = idx & 4095;
        int n = rem >> 4, kk = rem & 15;
        int k = c * 16 + kk;
        g_W1f[idx] = __float2half_rn((k < 324) ? W1[k * 256 + n] : 0.f);
    } else {
        int j = idx - 21 * 4096;
        if (j < 16 * 2048) {
            int c = j >> 11, rem = j & 2047;
            int n = rem >> 4, kk = rem & 15;
            int k = c * 16 + kk;
            g_W2f[j] = __float2half_rn(W2[k * 128 + n]);
        }
    }
}

// ============================================================
// fused GEMM1 -> ReLU -> GEMM2, plain fp16 MMA (1 MMA per k-step)
// CTA: 512 threads (16 warps), 128 rows. grid (128, 16).
// ============================================================
__global__ void __launch_bounds__(512, 1) gemm_mma_kernel(
    const float* __restrict__ fgc, const float* __restrict__ fgt,
    const float* __restrict__ bgc, const float* __restrict__ bgt,
    const float* __restrict__ b1, const float* __restrict__ b2)
{
    extern __shared__ char sm[];
    const uint32_t smb = smem_u32(sm);
    const int tid = threadIdx.x, lane = tid & 31, warp = tid >> 5;
    const int wm = warp & 3, wn = warp >> 2;
    const int b = blockIdx.y;
    const int row0 = blockIdx.x * 128;
    const int g = lane >> 2, tg = lane & 3;

    const int gr = tid & 127;
    const int gk0 = tid >> 7;
    const int R = row0 + gr;

    float acc[2][8][4];
    #pragma unroll
    for (int i = 0; i < 2; ++i)
        #pragma unroll
        for (int j = 0; j < 8; ++j)
            #pragma unroll
            for (int r = 0; r < 4; ++r) acc[i][j][r] = 0.f;

    // ---- prologue: fill stage1 buf 0 ----
    {
        #pragma unroll
        for (int q = 0; q < 4; ++q) {
            int k = gk0 + q * 4;
            int t = k / 12, rem = k - t * 12, s = rem / 3, cm = rem - s * 3;
            const float* sp = selsrc(s, fgc, fgt, bgc, bgt);
            float v = sp[((size_t)(b * 27 + t) * ROWS + R) * 3 + cm];
            *(__half*)(sm + A1F(0) + gr * 48 + k * 2) = __float2half_rn(v);
        }
        int n = tid >> 1, half = tid & 1;
        uint4 vh = ((const uint4*)(g_W1f))[tid];
        *(uint4*)(sm + B1F(0) + n * 48 + half * 16) = vh;
    }
    __syncthreads();

    // ---- stage 1: 21 chunks of k16 ----
    for (int c = 0; c < 21; ++c) {
        const int bi = c & 1;
        const bool hn = (c < 20);
        float av[4];
        uint4 wh;
        if (hn) {
            const int cn = c + 1;
            #pragma unroll
            for (int q = 0; q < 4; ++q) {
                int k = cn * 16 + gk0 + q * 4;
                float v = 0.f;
                if (k < 324) {
                    int t = k / 12, rem = k - t * 12, s = rem / 3, cm = rem - s * 3;
                    const float* sp = selsrc(s, fgc, fgt, bgc, bgt);
                    v = sp[((size_t)(b * 27 + t) * ROWS + R) * 3 + cm];
                }
                av[q] = v;
            }
            wh = ((const uint4*)(g_W1f + cn * 4096))[tid];
        }

        uint32_t ah[2][4];
        {
            uint32_t aAddr = smb + A1F(bi)
                + (uint32_t)((wm * 32 + (lane & 15)) * 48 + (lane >> 4) * 16);
            ldmat4(aAddr, ah[0]);
            ldmat4(aAddr + 16 * 48, ah[1]);
        }
        uint32_t bAddr = smb + B1F(bi)
            + (uint32_t)((wn * 64 + (lane & 15)) * 48 + (lane >> 4) * 16);
        #pragma unroll
        for (int jj = 0; jj < 4; ++jj) {
            uint32_t bh[4];
            ldmat4(bAddr + jj * 16 * 48, bh);
            #pragma unroll
            for (int i = 0; i < 2; ++i) {
                #pragma unroll
                for (int jn = 0; jn < 2; ++jn)
                    mma16816(acc[i][jj * 2 + jn], ah[i], bh[jn], bh[jn + 2]);
            }
        }

        if (hn) {
            const int nbi = bi ^ 1;
            #pragma unroll
            for (int q = 0; q < 4; ++q) {
                int k = gk0 + q * 4;
                *(__half*)(sm + A1F(nbi) + gr * 48 + k * 2) = __float2half_rn(av[q]);
            }
            int n = tid >> 1, half = tid & 1;
            *(uint4*)(sm + B1F(nbi) + n * 48 + half * 16) = wh;
        }
        __syncthreads();
    }

    // ---- epilogue 1: bias + relu + fp16 -> C1 smem ----
    #pragma unroll
    for (int i = 0; i < 2; ++i) {
        int m0 = wm * 32 + i * 16 + g;
        #pragma unroll
        for (int j = 0; j < 8; ++j) {
            int n = wn * 64 + j * 8 + tg * 2;
            float bn0 = b1[n], bn1 = b1[n + 1];
            float x0 = fmaxf(acc[i][j][0] + bn0, 0.f);
            float x1 = fmaxf(acc[i][j][1] + bn1, 0.f);
            float x2 = fmaxf(acc[i][j][2] + bn0, 0.f);
            float x3 = fmaxf(acc[i][j][3] + bn1, 0.f);
            *(uint32_t*)(sm + C1H + m0 * 528 + n * 2)       = packh2(x0, x1);
            *(uint32_t*)(sm + C1H + (m0 + 8) * 528 + n * 2) = packh2(x2, x3);
        }
    }
    __syncthreads();

    // ---- stage 2: C2 = C1 @ W2, K=256 (16 chunks) ----
    float acc2[2][4][4];
    #pragma unroll
    for (int i = 0; i < 2; ++i)
        #pragma unroll
        for (int j = 0; j < 4; ++j)
            #pragma unroll
            for (int r = 0; r < 4; ++r) acc2[i][j][r] = 0.f;

    if (tid < 256) {
        int n = tid >> 1, half = tid & 1;
        uint4 v = ((const uint4*)(g_W2f))[tid];
        *(uint4*)(sm + B2F(0) + n * 48 + half * 16) = v;
    }
    __syncthreads();

    for (int c = 0; c < 16; ++c) {
        const int bi = c & 1;
        const bool hn = (c < 15);
        uint4 wv;
        if (hn && tid < 256)
            wv = ((const uint4*)(g_W2f + (c + 1) * 2048))[tid];

        uint32_t ah[2][4];
        {
            uint32_t aAddr = smb + C1H
                + (uint32_t)((wm * 32 + (lane & 15)) * 528 + c * 32 + (lane >> 4) * 16);
            ldmat4(aAddr, ah[0]);
            ldmat4(aAddr + 16 * 528, ah[1]);
        }
        uint32_t bAddr = smb + B2F(bi)
            + (uint32_t)((wn * 32 + (lane & 15)) * 48 + (lane >> 4) * 16);
        #pragma unroll
        for (int jj = 0; jj < 2; ++jj) {
            uint32_t bh[4];
            ldmat4(bAddr + jj * 16 * 48, bh);
            #pragma unroll
            for (int i = 0; i < 2; ++i) {
                #pragma unroll
                for (int jn = 0; jn < 2; ++jn)
                    mma16816(acc2[i][jj * 2 + jn], ah[i], bh[jn], bh[jn + 2]);
            }
        }

        if (hn && tid < 256) {
            int n = tid >> 1, half = tid & 1;
            *(uint4*)(sm + B2F(bi ^ 1) + n * 48 + half * 16) = wv;
        }
        __syncthreads();
    }

    // ---- epilogue 2: + b2 -> fp16 staging smem [z][m] (pitch 272B) ----
    #pragma unroll
    for (int i = 0; i < 2; ++i) {
        int m0 = wm * 32 + i * 16 + g;
        #pragma unroll
        for (int j = 0; j < 4; ++j) {
            int z = wn * 32 + j * 8 + tg * 2;
            float bz0 = b2[z], bz1 = b2[z + 1];
            *(__half*)(sm + STG + z * 272 + m0 * 2)           = __float2half_rn(acc2[i][j][0] + bz0);
            *(__half*)(sm + STG + (z + 1) * 272 + m0 * 2)     = __float2half_rn(acc2[i][j][1] + bz1);
            *(__half*)(sm + STG + z * 272 + (m0 + 8) * 2)     = __float2half_rn(acc2[i][j][2] + bz0);
            *(__half*)(sm + STG + (z + 1) * 272 + (m0 + 8) * 2) = __float2half_rn(acc2[i][j][3] + bz1);
        }
    }
    __syncthreads();

    // coalesced copy: 128 z x 256B
    #pragma unroll
    for (int e = tid; e < 2048; e += 512) {
        int z = e >> 4, q = e & 15;
        uint4 v = *(uint4*)(sm + STG + z * 272 + q * 16);
        *(uint4*)(g_Hh + ((size_t)b * 128 + z) * ROWS + row0 + q * 8) = v;
    }
}

// ============================================================
// invariant pooling + vector_log (CTA per (b,z)), fp16 input
// ============================================================
__global__ void pool_kernel()
{
    extern __shared__ float S[];
    const int tid = threadIdx.x;
    const int bz = blockIdx.x;
    const __half2* src = (const __half2*)(g_Hh + (size_t)bz * ROWS);
    for (int e = tid; e < 8192; e += 128) {
        float2 v = __half22float2(src[e]);
        int row = e >> 6, col = (e & 63) * 2;
        S[row * 129 + col] = v.x;
        S[row * 129 + col + 1] = v.y;
    }
    __syncthreads();
    const int a = tid;
    const float* rowp = S + a * 129;
    float d = rowp[a], r = 0.f, c = 0.f, p4 = 0.f, p5 = 0.f;
    #pragma unroll 4
    for (int bb = 0; bb < 128; ++bb) {
        float xab = rowp[bb], xba = S[bb * 129 + a];
        r += xab; c += xba;
        p4 = fmaf(xab, xab, p4);
        p5 = fmaf(xab, xba, p5);
    }
    float vals[8] = { d, r, d * d, d * r, p4, p5, r * r, r * c };
    __syncthreads();
    float* red = S;
    #pragma unroll
    for (int q = 0; q < 8; ++q) {
        float v = vals[q];
        #pragma unroll
        for (int off = 16; off > 0; off >>= 1)
            v += __shfl_down_sync(0xffffffff, v, off);
        if ((tid & 31) == 0) red[(tid >> 5) * 8 + q] = v;
    }
    __syncthreads();
    if (tid < 8) {
        float h = red[tid] + red[8 + tid] + red[16 + tid] + red[24 + tid];
        const float denom[8] = {128.f, 16384.f, 128.f, 16384.f,
                                16384.f, 16384.f, 2097152.f, 2097152.f};
        float p = h / denom[tid];
        float vl = copysignf(log1pf(fabsf(p)) * 0.1f, p);
        g_P[(bz >> 7) * 1024 + tid * 128 + (bz & 127)] = vl;
    }
}

// ============================================================
// mlp2a: split-K partials (grid 16 x 16)
// ============================================================
__global__ void mlp2a_kernel(const float* __restrict__ W3)
{
    const int r = blockIdx.x, h = blockIdx.y;
    const int n = threadIdx.x;               // 256
    const float* p = g_P + r * 1024 + h * 64;
    const float* w = W3 + (size_t)h * 64 * 256;
    float acc = 0.f;
    #pragma unroll 8
    for (int k = 0; k < 64; ++k)
        acc = fmaf(p[k], w[k * 256 + n], acc);
    g_part[(r * 16 + h) * 256 + n] = acc;
}

// ============================================================
// mlp2b: reduce partials + bias/relu + final GEMV + tanh
// ============================================================
__global__ void mlp2b_kernel(const float* __restrict__ b3,
                             const float* __restrict__ W4, const float* __restrict__ b4,
                             float* __restrict__ out)
{
    __shared__ float H2[16 * 256];
    const int tid = threadIdx.x;              // 512
    for (int e = tid; e < 4096; e += 512) {
        int r = e >> 8, n = e & 255;
        float s = 0.f;
        #pragma unroll
        for (int h = 0; h < 16; ++h) s += g_part[(r * 16 + h) * 256 + n];
        H2[e] = fmaxf(s + b3[n], 0.f);
    }
    __syncthreads();
    const int o = tid >> 4, g = tid & 15;     // 32 outputs x 16-way
    const int r = o >> 1, c = o & 1;
    float s = 0.f;
    #pragma unroll 4
    for (int k = g; k < 256; k += 16)
        s = fmaf(H2[r * 256 + k], W4[k * 2 + c], s);
    s += __shfl_down_sync(0xffffffff, s, 8, 16);
    s += __shfl_down_sync(0xffffffff, s, 4, 16);
    s += __shfl_down_sync(0xffffffff, s, 2, 16);
    s += __shfl_down_sync(0xffffffff, s, 1, 16);
    if (g == 0) out[o] = tanhf(s + b4[c]) * 8.0f;
}

// ============================================================
extern "C" void kernel_launch(void* const* d_in, const int* in_sizes, int n_in,
                              void* d_out, int out_size)
{
    const float* fgc = (const float*)d_in[0];
    const float* fgt = (const float*)d_in[1];
    const float* bgc = (const float*)d_in[2];
    const float* bgt = (const float*)d_in[3];
    const float* W1  = (const float*)d_in[4];
    const float* b1  = (const float*)d_in[5];
    const float* W2  = (const float*)d_in[6];
    const float* b2  = (const float*)d_in[7];
    const float* W3  = (const float*)d_in[8];
    const float* b3  = (const float*)d_in[9];
    const float* W4  = (const float*)d_in[10];
    const float* b4  = (const float*)d_in[11];
    float* out = (float*)d_out;

    cudaFuncSetAttribute(gemm_mma_kernel, cudaFuncAttributeMaxDynamicSharedMemorySize, SMEM_TOTAL);
    cudaFuncSetAttribute(pool_kernel,     cudaFuncAttributeMaxDynamicSharedMemorySize, 128 * 129 * 4);

    prep_w_kernel<<<464, 256>>>(W1, W2);
    gemm_mma_kernel<<<dim3(128, NB), 512, SMEM_TOTAL>>>(fgc, fgt, bgc, bgt, b1, b2);
    pool_kernel<<<NB * 128, 128, 128 * 129 * 4>>>();
    mlp2a_kernel<<<dim3(16, 16), 256>>>(W3);
    mlp2b_kernel<<<1, 512>>>(b3, W4, b4, out);
}

// round 7
// speedup vs baseline: 5.9524x; 1.0508x over previous
#include <cuda_runtime.h>
#include <cuda_fp16.h>
#include <math.h>
#include <stdint.h>

#define NB 16
#define ROWS 16384

// ---------------- device scratch ----------------
__device__ __align__(16) __half g_Hh[(size_t)NB * 128 * ROWS];  // [b][z][row] fp16
__device__ float g_P[NB * 1024];
__device__ float g_part[NB * 16 * 256];
__device__ __align__(16) __half g_W1f[21 * 256 * 16];  // [c][n][kk]
__device__ __align__(16) __half g_W2f[16 * 128 * 16];  // [c][n][kk]

// ---------------- smem layout (bytes), 64-row CTA ----------------
#define C1H 0                         // 64 x 264 halves (pitch 528B) = 33792
#define S1  33792
#define A1F(bi) (S1 + (bi) * 15360)   // A tile 64x16 half, pitch 48B = 3072
#define B1F(bi) (A1F(bi) + 3072)      // B tile 256x16 half, pitch 48B = 12288
#define B2F(bi) (S1 + (bi) * 6144)    // stage2 B reuses stage1 region
#define STG 0                         // epilogue-2 staging reuses C1: 128 x 144B = 18432
#define SMEM_TOTAL 64512

// ---------------- helpers ----------------
__device__ __forceinline__ uint32_t smem_u32(const void* p) {
    uint32_t a;
    asm("{ .reg .u64 t; cvta.to.shared.u64 t, %1; cvt.u32.u64 %0, t; }" : "=r"(a) : "l"(p));
    return a;
}
__device__ __forceinline__ void ldmat4(uint32_t addr, uint32_t r[4]) {
    asm volatile("ldmatrix.sync.aligned.m8n8.x4.shared.b16 {%0,%1,%2,%3}, [%4];"
        : "=r"(r[0]), "=r"(r[1]), "=r"(r[2]), "=r"(r[3]) : "r"(addr) : "memory");
}
__device__ __forceinline__ void mma16816(float d[4], const uint32_t a[4],
                                         uint32_t b0, uint32_t b1) {
    asm volatile("mma.sync.aligned.m16n8k16.row.col.f32.f16.f16.f32 "
        "{%0,%1,%2,%3}, {%4,%5,%6,%7}, {%8,%9}, {%0,%1,%2,%3};"
        : "+f"(d[0]), "+f"(d[1]), "+f"(d[2]), "+f"(d[3])
        : "r"(a[0]), "r"(a[1]), "r"(a[2]), "r"(a[3]), "r"(b0), "r"(b1));
}
__device__ __forceinline__ uint32_t packh2(float x, float y) {
    __half2 h = __floats2half2_rn(x, y);
    return *(uint32_t*)&h;
}
__device__ __forceinline__ const float* selsrc(int s, const float* a, const float* b,
                                               const float* c, const float* d) {
    return s == 0 ? a : (s == 1 ? b : (s == 2 ? c : d));
}

// ============================================================
// prep: W1/W2 -> fp16, pre-chunked [c][n][kk]
// ============================================================
__global__ void prep_w_kernel(const float* __restrict__ W1, const float* __restrict__ W2)
{
    int idx = blockIdx.x * 256 + threadIdx.x;
    if (idx < 21 * 4096) {
        int c = idx >> 12, rem = idx & 4095;
        int n = rem >> 4, kk = rem & 15;
        int k = c * 16 + kk;
        g_W1f[idx] = __float2half_rn((k < 324) ? W1[k * 256 + n] : 0.f);
    } else {
        int j = idx - 21 * 4096;
        if (j < 16 * 2048) {
            int c = j >> 11, rem = j & 2047;
            int n = rem >> 4, kk = rem & 15;
            int k = c * 16 + kk;
            g_W2f[j] = __float2half_rn(W2[k * 128 + n]);
        }
    }
}

// ============================================================
// fused GEMM1 -> ReLU -> GEMM2, fp16 MMA
// CTA: 256 threads (8 warps: 2 along M x 4 along N), 64 rows. grid (256, 16).
// 2 CTAs/SM -> cross-CTA latency hiding.
// ============================================================
__global__ void __launch_bounds__(256, 2) gemm_mma_kernel(
    const float* __restrict__ fgc, const float* __restrict__ fgt,
    const float* __restrict__ bgc, const float* __restrict__ bgt,
    const float* __restrict__ b1, const float* __restrict__ b2)
{
    extern __shared__ char sm[];
    const uint32_t smb = smem_u32(sm);
    const int tid = threadIdx.x, lane = tid & 31, warp = tid >> 5;
    const int wm = warp & 1, wn = warp >> 1;          // 2 x 4
    const int b = blockIdx.y;
    const int row0 = blockIdx.x * 64;
    const int g = lane >> 2, tg = lane & 3;

    const int gr = tid & 63;
    const int gk0 = tid >> 6;                         // 0..3
    const int R = row0 + gr;

    float acc[2][8][4];
    #pragma unroll
    for (int i = 0; i < 2; ++i)
        #pragma unroll
        for (int j = 0; j < 8; ++j)
            #pragma unroll
            for (int r = 0; r < 4; ++r) acc[i][j][r] = 0.f;

    // ---- prologue: fill stage1 buf 0 ----
    {
        #pragma unroll
        for (int q = 0; q < 4; ++q) {
            int k = gk0 + q * 4;
            int t = k / 12, rem = k - t * 12, s = rem / 3, cm = rem - s * 3;
            const float* sp = selsrc(s, fgc, fgt, bgc, bgt);
            float v = sp[((size_t)(b * 27 + t) * ROWS + R) * 3 + cm];
            *(__half*)(sm + A1F(0) + gr * 48 + k * 2) = __float2half_rn(v);
        }
        #pragma unroll
        for (int e = tid; e < 512; e += 256) {
            int n = e >> 1, half = e & 1;
            uint4 vh = ((const uint4*)(g_W1f))[e];
            *(uint4*)(sm + B1F(0) + n * 48 + half * 16) = vh;
        }
    }
    __syncthreads();

    // ---- stage 1: 21 chunks of k16 ----
    for (int c = 0; c < 21; ++c) {
        const int bi = c & 1;
        const bool hn = (c < 20);
        float av[4];
        uint4 wh[2];
        if (hn) {
            const int cn = c + 1;
            #pragma unroll
            for (int q = 0; q < 4; ++q) {
                int k = cn * 16 + gk0 + q * 4;
                float v = 0.f;
                if (k < 324) {
                    int t = k / 12, rem = k - t * 12, s = rem / 3, cm = rem - s * 3;
                    const float* sp = selsrc(s, fgc, fgt, bgc, bgt);
                    v = sp[((size_t)(b * 27 + t) * ROWS + R) * 3 + cm];
                }
                av[q] = v;
            }
            wh[0] = ((const uint4*)(g_W1f + cn * 4096))[tid];
            wh[1] = ((const uint4*)(g_W1f + cn * 4096))[tid + 256];
        }

        uint32_t ah[2][4];
        {
            uint32_t aAddr = smb + A1F(bi)
                + (uint32_t)((wm * 32 + (lane & 15)) * 48 + (lane >> 4) * 16);
            ldmat4(aAddr, ah[0]);
            ldmat4(aAddr + 16 * 48, ah[1]);
        }
        uint32_t bAddr = smb + B1F(bi)
            + (uint32_t)((wn * 64 + (lane & 15)) * 48 + (lane >> 4) * 16);
        #pragma unroll
        for (int jj = 0; jj < 4; ++jj) {
            uint32_t bh[4];
            ldmat4(bAddr + jj * 16 * 48, bh);
            #pragma unroll
            for (int i = 0; i < 2; ++i) {
                #pragma unroll
                for (int jn = 0; jn < 2; ++jn)
                    mma16816(acc[i][jj * 2 + jn], ah[i], bh[jn], bh[jn + 2]);
            }
        }

        if (hn) {
            const int nbi = bi ^ 1;
            #pragma unroll
            for (int q = 0; q < 4; ++q) {
                int k = gk0 + q * 4;
                *(__half*)(sm + A1F(nbi) + gr * 48 + k * 2) = __float2half_rn(av[q]);
            }
            #pragma unroll
            for (int u = 0; u < 2; ++u) {
                int e = tid + u * 256;
                int n = e >> 1, half = e & 1;
                *(uint4*)(sm + B1F(nbi) + n * 48 + half * 16) = wh[u];
            }
        }
        __syncthreads();
    }

    // ---- epilogue 1: bias + relu + fp16 -> C1 smem ----
    #pragma unroll
    for (int i = 0; i < 2; ++i) {
        int m0 = wm * 32 + i * 16 + g;
        #pragma unroll
        for (int j = 0; j < 8; ++j) {
            int n = wn * 64 + j * 8 + tg * 2;
            float bn0 = b1[n], bn1 = b1[n + 1];
            float x0 = fmaxf(acc[i][j][0] + bn0, 0.f);
            float x1 = fmaxf(acc[i][j][1] + bn1, 0.f);
            float x2 = fmaxf(acc[i][j][2] + bn0, 0.f);
            float x3 = fmaxf(acc[i][j][3] + bn1, 0.f);
            *(uint32_t*)(sm + C1H + m0 * 528 + n * 2)       = packh2(x0, x1);
            *(uint32_t*)(sm + C1H + (m0 + 8) * 528 + n * 2) = packh2(x2, x3);
        }
    }
    __syncthreads();

    // ---- stage 2: C2 = C1 @ W2, K=256 (16 chunks) ----
    float acc2[2][4][4];
    #pragma unroll
    for (int i = 0; i < 2; ++i)
        #pragma unroll
        for (int j = 0; j < 4; ++j)
            #pragma unroll
            for (int r = 0; r < 4; ++r) acc2[i][j][r] = 0.f;

    {   // prologue: W2 chunk 0 (4 KB = 256 uint4)
        int n = tid >> 1, half = tid & 1;
        uint4 v = ((const uint4*)(g_W2f))[tid];
        *(uint4*)(sm + B2F(0) + n * 48 + half * 16) = v;
    }
    __syncthreads();

    for (int c = 0; c < 16; ++c) {
        const int bi = c & 1;
        const bool hn = (c < 15);
        uint4 wv;
        if (hn)
            wv = ((const uint4*)(g_W2f + (c + 1) * 2048))[tid];

        uint32_t ah[2][4];
        {
            uint32_t aAddr = smb + C1H
                + (uint32_t)((wm * 32 + (lane & 15)) * 528 + c * 32 + (lane >> 4) * 16);
            ldmat4(aAddr, ah[0]);
            ldmat4(aAddr + 16 * 528, ah[1]);
        }
        uint32_t bAddr = smb + B2F(bi)
            + (uint32_t)((wn * 32 + (lane & 15)) * 48 + (lane >> 4) * 16);
        #pragma unroll
        for (int jj = 0; jj < 2; ++jj) {
            uint32_t bh[4];
            ldmat4(bAddr + jj * 16 * 48, bh);
            #pragma unroll
            for (int i = 0; i < 2; ++i) {
                #pragma unroll
                for (int jn = 0; jn < 2; ++jn)
                    mma16816(acc2[i][jj * 2 + jn], ah[i], bh[jn], bh[jn + 2]);
            }
        }

        if (hn) {
            int n = tid >> 1, half = tid & 1;
            *(uint4*)(sm + B2F(bi ^ 1) + n * 48 + half * 16) = wv;
        }
        __syncthreads();
    }

    // ---- epilogue 2: + b2 -> fp16 staging smem [z][m] (pitch 144B) ----
    #pragma unroll
    for (int i = 0; i < 2; ++i) {
        int m0 = wm * 32 + i * 16 + g;
        #pragma unroll
        for (int j = 0; j < 4; ++j) {
            int z = wn * 32 + j * 8 + tg * 2;
            float bz0 = b2[z], bz1 = b2[z + 1];
            *(__half*)(sm + STG + z * 144 + m0 * 2)             = __float2half_rn(acc2[i][j][0] + bz0);
            *(__half*)(sm + STG + (z + 1) * 144 + m0 * 2)       = __float2half_rn(acc2[i][j][1] + bz1);
            *(__half*)(sm + STG + z * 144 + (m0 + 8) * 2)       = __float2half_rn(acc2[i][j][2] + bz0);
            *(__half*)(sm + STG + (z + 1) * 144 + (m0 + 8) * 2) = __float2half_rn(acc2[i][j][3] + bz1);
        }
    }
    __syncthreads();

    // coalesced copy: 128 z x 128B
    #pragma unroll
    for (int e = tid; e < 1024; e += 256) {
        int z = e >> 3, q = e & 7;
        uint4 v = *(uint4*)(sm + STG + z * 144 + q * 16);
        *(uint4*)(g_Hh + ((size_t)b * 128 + z) * ROWS + row0 + q * 8) = v;
    }
}

// ============================================================
// invariant pooling + vector_log (CTA per (b,z)), fp16 input
// ============================================================
__global__ void pool_kernel()
{
    extern __shared__ float S[];
    const int tid = threadIdx.x;
    const int bz = blockIdx.x;
    const __half2* src = (const __half2*)(g_Hh + (size_t)bz * ROWS);
    for (int e = tid; e < 8192; e += 128) {
        float2 v = __half22float2(src[e]);
        int row = e >> 6, col = (e & 63) * 2;
        S[row * 129 + col] = v.x;
        S[row * 129 + col + 1] = v.y;
    }
    __syncthreads();
    const int a = tid;
    const float* rowp = S + a * 129;
    float d = rowp[a], r = 0.f, c = 0.f, p4 = 0.f, p5 = 0.f;
    #pragma unroll 4
    for (int bb = 0; bb < 128; ++bb) {
        float xab = rowp[bb], xba = S[bb * 129 + a];
        r += xab; c += xba;
        p4 = fmaf(xab, xab, p4);
        p5 = fmaf(xab, xba, p5);
    }
    float vals[8] = { d, r, d * d, d * r, p4, p5, r * r, r * c };
    __syncthreads();
    float* red = S;
    #pragma unroll
    for (int q = 0; q < 8; ++q) {
        float v = vals[q];
        #pragma unroll
        for (int off = 16; off > 0; off >>= 1)
            v += __shfl_down_sync(0xffffffff, v, off);
        if ((tid & 31) == 0) red[(tid >> 5) * 8 + q] = v;
    }
    __syncthreads();
    if (tid < 8) {
        float h = red[tid] + red[8 + tid] + red[16 + tid] + red[24 + tid];
        const float denom[8] = {128.f, 16384.f, 128.f, 16384.f,
                                16384.f, 16384.f, 2097152.f, 2097152.f};
        float p = h / denom[tid];
        float vl = copysignf(log1pf(fabsf(p)) * 0.1f, p);
        g_P[(bz >> 7) * 1024 + tid * 128 + (bz & 127)] = vl;
    }
}

// ============================================================
// mlp2a: split-K partials (grid 16 x 16)
// ============================================================
__global__ void mlp2a_kernel(const float* __restrict__ W3)
{
    const int r = blockIdx.x, h = blockIdx.y;
    const int n = threadIdx.x;               // 256
    const float* p = g_P + r * 1024 + h * 64;
    const float* w = W3 + (size_t)h * 64 * 256;
    float acc = 0.f;
    #pragma unroll 8
    for (int k = 0; k < 64; ++k)
        acc = fmaf(p[k], w[k * 256 + n], acc);
    g_part[(r * 16 + h) * 256 + n] = acc;
}

// ============================================================
// mlp2b: reduce partials + bias/relu + final GEMV + tanh
// ============================================================
__global__ void mlp2b_kernel(const float* __restrict__ b3,
                             const float* __restrict__ W4, const float* __restrict__ b4,
                             float* __restrict__ out)
{
    __shared__ float H2[16 * 256];
    const int tid = threadIdx.x;              // 512
    for (int e = tid; e < 4096; e += 512) {
        int r = e >> 8, n = e & 255;
        float s = 0.f;
        #pragma unroll
        for (int h = 0; h < 16; ++h) s += g_part[(r * 16 + h) * 256 + n];
        H2[e] = fmaxf(s + b3[n], 0.f);
    }
    __syncthreads();
    const int o = tid >> 4, g = tid & 15;     // 32 outputs x 16-way
    const int r = o >> 1, c = o & 1;
    float s = 0.f;
    #pragma unroll 4
    for (int k = g; k < 256; k += 16)
        s = fmaf(H2[r * 256 + k], W4[k * 2 + c], s);
    s += __shfl_down_sync(0xffffffff, s, 8, 16);
    s += __shfl_down_sync(0xffffffff, s, 4, 16);
    s += __shfl_down_sync(0xffffffff, s, 2, 16);
    s += __shfl_down_sync(0xffffffff, s, 1, 16);
    if (g == 0) out[o] = tanhf(s + b4[c]) * 8.0f;
}

// ============================================================
extern "C" void kernel_launch(void* const* d_in, const int* in_sizes, int n_in,
                              void* d_out, int out_size)
{
    const float* fgc = (const float*)d_in[0];
    const float* fgt = (const float*)d_in[1];
    const float* bgc = (const float*)d_in[2];
    const float* bgt = (const float*)d_in[3];
    const float* W1  = (const float*)d_in[4];
    const float* b1  = (const float*)d_in[5];
    const float* W2  = (const float*)d_in[6];
    const float* b2  = (const float*)d_in[7];
    const float* W3  = (const float*)d_in[8];
    const float* b3  = (const float*)d_in[9];
    const float* W4  = (const float*)d_in[10];
    const float* b4  = (const float*)d_in[11];
    float* out = (float*)d_out;

    cudaFuncSetAttribute(gemm_mma_kernel, cudaFuncAttributeMaxDynamicSharedMemorySize, SMEM_TOTAL);
    cudaFuncSetAttribute(pool_kernel,     cudaFuncAttributeMaxDynamicSharedMemorySize, 128 * 129 * 4);

    prep_w_kernel<<<464, 256>>>(W1, W2);
    gemm_mma_kernel<<<dim3(256, NB), 256, SMEM_TOTAL>>>(fgc, fgt, bgc, bgt, b1, b2);
    pool_kernel<<<NB * 128, 128, 128 * 129 * 4>>>();
    mlp2a_kernel<<<dim3(16, 16), 256>>>(W3);
    mlp2b_kernel<<<1, 512>>>(b3, W4, b4, out);
}